// round 8
// baseline (speedup 1.0000x reference)
#include <cuda_runtime.h>

// EGNN forward, N=50000, E=1.6M, H=32, DX=16, L=2.
// R7: edge-MLP weights pre-packed (f32x2) into __device__ global arrays,
//     loaded via uniform-address LDG.128 (rt 1.82 SM-wide) instead of LDS
//     (rt 4 SM-wide, the measured R4 bottleneck). No smem in edge kernel.

#define H    32
#define DX   16
#define HQ   (H / 2)
#define NMAX 50048

typedef unsigned long long u64;

__device__ __align__(16) float g_x[NMAX * DX];
__device__ __align__(16) float g_h[NMAX * H];
__device__ __align__(16) float g_A[NMAX * H];
__device__ __align__(16) float g_B[NMAX * H];
__device__ __align__(16) float g_magg[NMAX * H];
__device__ __align__(16) float g_tagg[NMAX * DX];
__device__ float g_cnt[NMAX];
__device__ int g_dummy;

// packed edge-MLP weights (filled by prep_kernel each replay)
__device__ __align__(16) u64 g_pW2[2][H][HQ];    // (W2[2jq][k], W2[2jq+1][k])
__device__ __align__(16) u64 g_pcW1[2][H][HQ];
__device__ __align__(16) u64 g_pwr[2][HQ];
__device__ __align__(16) u64 g_pwe[2][3][HQ];
__device__ __align__(16) u64 g_pb2[2][HQ];
__device__ __align__(16) u64 g_pcb1[2][HQ];
__device__ __align__(16) float g_pcw2[2][H];

__device__ __forceinline__ float silu_f(float v) {
    return v * (1.0f / (1.0f + __expf(-v)));
}

// ---- f32x2 packed helpers ---------------------------------------------------
__device__ __forceinline__ u64 pack2(float lo, float hi) {
    u64 r; asm("mov.b64 %0, {%1,%2};" : "=l"(r) : "f"(lo), "f"(hi)); return r;
}
__device__ __forceinline__ u64 dup2(float v) {
    u64 r; asm("mov.b64 %0, {%1,%1};" : "=l"(r) : "f"(v)); return r;
}
__device__ __forceinline__ void unpack2(u64 v, float& lo, float& hi) {
    asm("mov.b64 {%0,%1}, %2;" : "=f"(lo), "=f"(hi) : "l"(v));
}
__device__ __forceinline__ void fma2(u64& d, u64 a, u64 b) {
    asm("fma.rn.f32x2 %0, %1, %2, %0;" : "+l"(d) : "l"(a), "l"(b));
}
__device__ __forceinline__ u64 add2(u64 a, u64 b) {
    u64 r; asm("add.rn.f32x2 %0, %1, %2;" : "=l"(r) : "l"(a), "l"(b)); return r;
}

__device__ __forceinline__ void red_add_v4(float* addr, float a, float b, float c, float d) {
    asm volatile("red.global.add.v4.f32 [%0], {%1,%2,%3,%4};"
                 :: "l"(addr), "f"(a), "f"(b), "f"(c), "f"(d)
                 : "memory");
}

// ---------------------------------------------------------------------------
// prep: pack edge-MLP weights into f32x2 global arrays
// ---------------------------------------------------------------------------
__global__ __launch_bounds__(256) void prep_kernel(
    const float* __restrict__ eW1,  // [2][32][68]
    const float* __restrict__ eW2,  // [2][32][32]
    const float* __restrict__ eb2,  // [2][32]
    const float* __restrict__ cW1,  // [2][32][32]
    const float* __restrict__ cb1,  // [2][32]
    const float* __restrict__ cW2)  // [2][32]
{
    for (int idx = threadIdx.x; idx < 2 * H * HQ; idx += 256) {
        int l = idx / (H * HQ);
        int r = idx % (H * HQ);
        int k = r / HQ, jq = r % HQ;
        const float* W2 = eW2 + l * H * H;
        const float* C1 = cW1 + l * H * H;
        g_pW2[l][k][jq]  = pack2(W2[(2 * jq) * H + k], W2[(2 * jq + 1) * H + k]);
        g_pcW1[l][k][jq] = pack2(C1[(2 * jq) * H + k], C1[(2 * jq + 1) * H + k]);
    }
    for (int idx = threadIdx.x; idx < 2 * HQ; idx += 256) {
        int l = idx / HQ, jq = idx % HQ;
        const float* W1 = eW1 + l * H * 68;
        g_pwr[l][jq]    = pack2(W1[(2 * jq) * 68 + 64], W1[(2 * jq + 1) * 68 + 64]);
        g_pwe[l][0][jq] = pack2(W1[(2 * jq) * 68 + 65], W1[(2 * jq + 1) * 68 + 65]);
        g_pwe[l][1][jq] = pack2(W1[(2 * jq) * 68 + 66], W1[(2 * jq + 1) * 68 + 66]);
        g_pwe[l][2][jq] = pack2(W1[(2 * jq) * 68 + 67], W1[(2 * jq + 1) * 68 + 67]);
        g_pb2[l][jq]    = pack2(eb2[l * H + 2 * jq],  eb2[l * H + 2 * jq + 1]);
        g_pcb1[l][jq]   = pack2(cb1[l * H + 2 * jq],  cb1[l * H + 2 * jq + 1]);
    }
    for (int idx = threadIdx.x; idx < 2 * H; idx += 256)
        g_pcw2[idx / H][idx % H] = cW2[idx];
}

// ---------------------------------------------------------------------------
// init: x0, h0, A0/B0, zero aggregators and counts
// ---------------------------------------------------------------------------
__global__ __launch_bounds__(128, 4) void init_kernel(
    const float* __restrict__ attrs,
    const float* __restrict__ pos,
    const float* __restrict__ projW,
    const float* __restrict__ embW,
    const float* __restrict__ embB,
    const float* __restrict__ eW1,    // layer0 edge_W1 [32][68]
    const float* __restrict__ eb1,
    int n)
{
    __shared__ __align__(16) float sWa[H][H];
    __shared__ __align__(16) float sWb[H][H];
    for (int idx = threadIdx.x; idx < H * H; idx += 128) {
        int j = idx >> 5, k = idx & 31;
        sWa[k][j] = eW1[j * 68 + k];
        sWb[k][j] = eW1[j * 68 + 32 + k];
    }
    __syncthreads();

    int i = blockIdx.x * 128 + threadIdx.x;
    if (i >= n) return;

    float p0 = pos[i * 3 + 0], p1 = pos[i * 3 + 1], p2 = pos[i * 3 + 2];
    float xv[DX];
#pragma unroll
    for (int j = 0; j < DX; j++)
        xv[j] = projW[j * 3 + 0] * p0 + projW[j * 3 + 1] * p1 + projW[j * 3 + 2] * p2;

    float4* xo = (float4*)&g_x[i * DX];
#pragma unroll
    for (int q = 0; q < 4; q++)
        xo[q] = make_float4(xv[4 * q], xv[4 * q + 1], xv[4 * q + 2], xv[4 * q + 3]);

    float a0 = attrs[i * 3 + 0], a1 = attrs[i * 3 + 1], a2 = attrs[i * 3 + 2];
    float hv[H];
#pragma unroll
    for (int j = 0; j < H; j++)
        hv[j] = embW[j * 3 + 0] * a0 + embW[j * 3 + 1] * a1 + embW[j * 3 + 2] * a2 + embB[j];

    float4* ho = (float4*)&g_h[i * H];
#pragma unroll
    for (int q = 0; q < 8; q++)
        ho[q] = make_float4(hv[4 * q], hv[4 * q + 1], hv[4 * q + 2], hv[4 * q + 3]);

    float Av[H], Bv[H];
#pragma unroll
    for (int j = 0; j < H; j++) { Av[j] = eb1[j]; Bv[j] = 0.0f; }
#pragma unroll
    for (int k = 0; k < H; k++) {
        float hk = hv[k];
        const float4* wa = (const float4*)&sWa[k][0];
        const float4* wb = (const float4*)&sWb[k][0];
#pragma unroll
        for (int q = 0; q < 8; q++) {
            float4 a = wa[q], b = wb[q];
            Av[4 * q + 0] += a.x * hk; Av[4 * q + 1] += a.y * hk;
            Av[4 * q + 2] += a.z * hk; Av[4 * q + 3] += a.w * hk;
            Bv[4 * q + 0] += b.x * hk; Bv[4 * q + 1] += b.y * hk;
            Bv[4 * q + 2] += b.z * hk; Bv[4 * q + 3] += b.w * hk;
        }
    }
    float4* Ao = (float4*)&g_A[i * H];
    float4* Bo = (float4*)&g_B[i * H];
#pragma unroll
    for (int q = 0; q < 8; q++) {
        Ao[q] = make_float4(Av[4 * q], Av[4 * q + 1], Av[4 * q + 2], Av[4 * q + 3]);
        Bo[q] = make_float4(Bv[4 * q], Bv[4 * q + 1], Bv[4 * q + 2], Bv[4 * q + 3]);
    }

    const float4 z4 = make_float4(0.f, 0.f, 0.f, 0.f);
    float4* mz = (float4*)&g_magg[i * H];
    float4* tz = (float4*)&g_tagg[i * DX];
#pragma unroll
    for (int q = 0; q < 8; q++) mz[q] = z4;
#pragma unroll
    for (int q = 0; q < 4; q++) tz[q] = z4;
    g_cnt[i] = 0.0f;
}

// ---------------------------------------------------------------------------
__global__ void count_kernel(const int* __restrict__ ei, int E)
{
    int e = blockIdx.x * blockDim.x + threadIdx.x;
    if (e < E) atomicAdd(&g_cnt[ei[e]], 1.0f);
}

// ---------------------------------------------------------------------------
// edge kernel: weights via uniform LDG.128 from packed global arrays
// ---------------------------------------------------------------------------
#define ETPB 128

template <int L>
__global__ __launch_bounds__(ETPB) void edge_kernel(
    const int* __restrict__ ei, int E,
    const float* __restrict__ pos)
{
    int e = blockIdx.x * ETPB + threadIdx.x;
    if (e >= E) return;

    int row = ei[e];
    int col = ei[E + e];

    float ea0 = pos[row * 3 + 0] - pos[col * 3 + 0];
    float ea1 = pos[row * 3 + 1] - pos[col * 3 + 1];
    float ea2 = pos[row * 3 + 2] - pos[col * 3 + 2];

    float cd[DX];
    const float4* xr = (const float4*)&g_x[row * DX];
    const float4* xc = (const float4*)&g_x[col * DX];
    float radial = 0.0f;
#pragma unroll
    for (int q = 0; q < 4; q++) {
        float4 a = xr[q], b = xc[q];
        float d0 = a.x - b.x, d1 = a.y - b.y, d2 = a.z - b.z, d3 = a.w - b.w;
        cd[4 * q + 0] = d0; cd[4 * q + 1] = d1; cd[4 * q + 2] = d2; cd[4 * q + 3] = d3;
        radial += d0 * d0 + d1 * d1 + d2 * d2 + d3 * d3;
    }

    // ---- layer 1 (A/B factored), packed ---------------------------------
    float acc[H];
    {
        const ulonglong2* Ar = (const ulonglong2*)&g_A[row * H];
        const ulonglong2* Bc = (const ulonglong2*)&g_B[col * H];
        u64 acc2[HQ];
#pragma unroll
        for (int q = 0; q < 8; q++) {
            ulonglong2 a = Ar[q], b = Bc[q];
            acc2[2 * q + 0] = add2(a.x, b.x);
            acc2[2 * q + 1] = add2(a.y, b.y);
        }
        u64 rad2 = dup2(radial);
        u64 e02 = dup2(ea0), e12 = dup2(ea1), e22 = dup2(ea2);
        const ulonglong2* wr4 = (const ulonglong2*)&g_pwr[L][0];
        const ulonglong2* w04 = (const ulonglong2*)&g_pwe[L][0][0];
        const ulonglong2* w14 = (const ulonglong2*)&g_pwe[L][1][0];
        const ulonglong2* w24 = (const ulonglong2*)&g_pwe[L][2][0];
#pragma unroll
        for (int q = 0; q < 8; q++) {
            ulonglong2 wr = wr4[q], w0 = w04[q], w1 = w14[q], w2 = w24[q];
            fma2(acc2[2 * q + 0], wr.x, rad2); fma2(acc2[2 * q + 1], wr.y, rad2);
            fma2(acc2[2 * q + 0], w0.x, e02);  fma2(acc2[2 * q + 1], w0.y, e02);
            fma2(acc2[2 * q + 0], w1.x, e12);  fma2(acc2[2 * q + 1], w1.y, e12);
            fma2(acc2[2 * q + 0], w2.x, e22);  fma2(acc2[2 * q + 1], w2.y, e22);
        }
#pragma unroll
        for (int jq = 0; jq < HQ; jq++) {
            float lo, hi;
            unpack2(acc2[jq], lo, hi);
            acc[2 * jq + 0] = silu_f(lo);
            acc[2 * jq + 1] = silu_f(hi);
        }
    }

    // ---- layer 2: m = silu(W2 m1 + b2), LDG weights ----------------------
    float m[H];
    {
        u64 m2[HQ];
        const ulonglong2* b4 = (const ulonglong2*)&g_pb2[L][0];
#pragma unroll
        for (int q = 0; q < 8; q++) {
            ulonglong2 b = b4[q];
            m2[2 * q + 0] = b.x; m2[2 * q + 1] = b.y;
        }
#pragma unroll
        for (int k = 0; k < H; k++) {
            u64 mk2 = dup2(acc[k]);
            const ulonglong2* w4 = (const ulonglong2*)&g_pW2[L][k][0];
#pragma unroll
            for (int q = 0; q < 8; q++) {
                ulonglong2 w = w4[q];
                fma2(m2[2 * q + 0], w.x, mk2);
                fma2(m2[2 * q + 1], w.y, mk2);
            }
        }
#pragma unroll
        for (int jq = 0; jq < HQ; jq++) {
            float lo, hi;
            unpack2(m2[jq], lo, hi);
            m[2 * jq + 0] = silu_f(lo);
            m[2 * jq + 1] = silu_f(hi);
        }
    }

    // ---- coord head, LDG weights ----------------------------------------
    float cm;
    {
        u64 c2[HQ];
        const ulonglong2* b4 = (const ulonglong2*)&g_pcb1[L][0];
#pragma unroll
        for (int q = 0; q < 8; q++) {
            ulonglong2 b = b4[q];
            c2[2 * q + 0] = b.x; c2[2 * q + 1] = b.y;
        }
#pragma unroll
        for (int k = 0; k < H; k++) {
            u64 mk2 = dup2(m[k]);
            const ulonglong2* w4 = (const ulonglong2*)&g_pcW1[L][k][0];
#pragma unroll
            for (int q = 0; q < 8; q++) {
                ulonglong2 w = w4[q];
                fma2(c2[2 * q + 0], w.x, mk2);
                fma2(c2[2 * q + 1], w.y, mk2);
            }
        }
        cm = 0.0f;
#pragma unroll
        for (int jq = 0; jq < HQ; jq++) {
            float lo, hi;
            unpack2(c2[jq], lo, hi);
            cm += g_pcw2[L][2 * jq + 0] * silu_f(lo);
            cm += g_pcw2[L][2 * jq + 1] * silu_f(hi);
        }
    }

    float* mago = &g_magg[row * H];
#pragma unroll
    for (int q = 0; q < 8; q++)
        red_add_v4(mago + 4 * q, m[4 * q], m[4 * q + 1], m[4 * q + 2], m[4 * q + 3]);

    float* tago = &g_tagg[row * DX];
#pragma unroll
    for (int q = 0; q < 4; q++)
        red_add_v4(tago + 4 * q,
                   cd[4 * q] * cm, cd[4 * q + 1] * cm, cd[4 * q + 2] * cm, cd[4 * q + 3] * cm);
}

// ---------------------------------------------------------------------------
// node kernel (R4 structure: smem weights, early gathers)
// ---------------------------------------------------------------------------
#define NTPB 128

__global__ __launch_bounds__(NTPB, 4) void node_kernel(
    const float* __restrict__ nW1,
    const float* __restrict__ nb1,
    const float* __restrict__ nW2,
    const float* __restrict__ nb2,
    const float* __restrict__ eW1n,
    const float* __restrict__ eb1n,
    const float* __restrict__ linW,
    float* __restrict__ out,
    int n)
{
    __shared__ __align__(16) float sN1t[2 * H][H];
    __shared__ __align__(16) float sN2t[H][H];
    __shared__ __align__(16) float sEAt[H][H];
    __shared__ __align__(16) float sEBt[H][H];

    int i = blockIdx.x * NTPB + threadIdx.x;
    bool active = (i < n);

    float cnt = 0.f;
    float4 xr[4], tr[4], hr[8], mr[8];
    if (active) {
        cnt = g_cnt[i];
        const float4* xp = (const float4*)&g_x[i * DX];
        const float4* tp = (const float4*)&g_tagg[i * DX];
        const float4* hp = (const float4*)&g_h[i * H];
        const float4* mp = (const float4*)&g_magg[i * H];
#pragma unroll
        for (int q = 0; q < 4; q++) { xr[q] = xp[q]; tr[q] = tp[q]; }
#pragma unroll
        for (int q = 0; q < 8; q++) { hr[q] = hp[q]; mr[q] = mp[q]; }
    }

    for (int idx = threadIdx.x; idx < H * 2 * H; idx += NTPB) {
        int j = idx >> 6, k = idx & 63;
        sN1t[k][j] = nW1[idx];
    }
    for (int idx = threadIdx.x; idx < H * H; idx += NTPB) {
        int j = idx >> 5, k = idx & 31;
        sN2t[k][j] = nW2[idx];
        if (eW1n) {
            sEAt[k][j] = eW1n[j * 68 + k];
            sEBt[k][j] = eW1n[j * 68 + 32 + k];
        }
    }
    __syncthreads();

    if (!active) return;

    float inv = 1.0f / fmaxf(cnt, 1.0f);
    const float4 z4 = make_float4(0.f, 0.f, 0.f, 0.f);

    float xv[DX];
    float4* xp = (float4*)&g_x[i * DX];
    float4* tp = (float4*)&g_tagg[i * DX];
#pragma unroll
    for (int q = 0; q < 4; q++) {
        xv[4 * q + 0] = xr[q].x + tr[q].x * inv;
        xv[4 * q + 1] = xr[q].y + tr[q].y * inv;
        xv[4 * q + 2] = xr[q].z + tr[q].z * inv;
        xv[4 * q + 3] = xr[q].w + tr[q].w * inv;
        xp[q] = make_float4(xv[4 * q], xv[4 * q + 1], xv[4 * q + 2], xv[4 * q + 3]);
        tp[q] = z4;
    }

    float hv[H], mg[H];
    float4* mp = (float4*)&g_magg[i * H];
#pragma unroll
    for (int q = 0; q < 8; q++) {
        hv[4 * q + 0] = hr[q].x; hv[4 * q + 1] = hr[q].y;
        hv[4 * q + 2] = hr[q].z; hv[4 * q + 3] = hr[q].w;
        mg[4 * q + 0] = mr[q].x; mg[4 * q + 1] = mr[q].y;
        mg[4 * q + 2] = mr[q].z; mg[4 * q + 3] = mr[q].w;
        mp[q] = z4;
    }

    float u[H];
#pragma unroll
    for (int j = 0; j < H; j++) u[j] = nb1[j];
#pragma unroll
    for (int k = 0; k < H; k++) {
        float v = hv[k];
        const float4* w4 = (const float4*)&sN1t[k][0];
#pragma unroll
        for (int q = 0; q < 8; q++) {
            float4 w = w4[q];
            u[4 * q + 0] += w.x * v; u[4 * q + 1] += w.y * v;
            u[4 * q + 2] += w.z * v; u[4 * q + 3] += w.w * v;
        }
    }
#pragma unroll
    for (int k = 0; k < H; k++) {
        float v = mg[k];
        const float4* w4 = (const float4*)&sN1t[H + k][0];
#pragma unroll
        for (int q = 0; q < 8; q++) {
            float4 w = w4[q];
            u[4 * q + 0] += w.x * v; u[4 * q + 1] += w.y * v;
            u[4 * q + 2] += w.z * v; u[4 * q + 3] += w.w * v;
        }
    }
#pragma unroll
    for (int j = 0; j < H; j++) u[j] = silu_f(u[j]);

    float hn[H];
#pragma unroll
    for (int j = 0; j < H; j++) hn[j] = nb2[j];
#pragma unroll
    for (int k = 0; k < H; k++) {
        float v = u[k];
        const float4* w4 = (const float4*)&sN2t[k][0];
#pragma unroll
        for (int q = 0; q < 8; q++) {
            float4 w = w4[q];
            hn[4 * q + 0] += w.x * v; hn[4 * q + 1] += w.y * v;
            hn[4 * q + 2] += w.z * v; hn[4 * q + 3] += w.w * v;
        }
    }
#pragma unroll
    for (int j = 0; j < H; j++) hn[j] += hv[j];
    float4* hp = (float4*)&g_h[i * H];
#pragma unroll
    for (int q = 0; q < 8; q++)
        hp[q] = make_float4(hn[4 * q], hn[4 * q + 1], hn[4 * q + 2], hn[4 * q + 3]);

    if (eW1n) {
        float Av[H], Bv[H];
#pragma unroll
        for (int j = 0; j < H; j++) { Av[j] = eb1n[j]; Bv[j] = 0.0f; }
#pragma unroll
        for (int k = 0; k < H; k++) {
            float v = hn[k];
            const float4* wa = (const float4*)&sEAt[k][0];
            const float4* wb = (const float4*)&sEBt[k][0];
#pragma unroll
            for (int q = 0; q < 8; q++) {
                float4 a = wa[q], b = wb[q];
                Av[4 * q + 0] += a.x * v; Av[4 * q + 1] += a.y * v;
                Av[4 * q + 2] += a.z * v; Av[4 * q + 3] += a.w * v;
                Bv[4 * q + 0] += b.x * v; Bv[4 * q + 1] += b.y * v;
                Bv[4 * q + 2] += b.z * v; Bv[4 * q + 3] += b.w * v;
            }
        }
        float4* Ao = (float4*)&g_A[i * H];
        float4* Bo = (float4*)&g_B[i * H];
#pragma unroll
        for (int q = 0; q < 8; q++) {
            Ao[q] = make_float4(Av[4 * q], Av[4 * q + 1], Av[4 * q + 2], Av[4 * q + 3]);
            Bo[q] = make_float4(Bv[4 * q], Bv[4 * q + 1], Bv[4 * q + 2], Bv[4 * q + 3]);
        }
    }

    if (linW) {
#pragma unroll
        for (int c = 0; c < 3; c++) {
            float acc = 0.0f;
#pragma unroll
            for (int k = 0; k < DX; k++) acc += linW[c * DX + k] * xv[k];
            out[i * 3 + c] = acc;
        }
    }
}

// ---------------------------------------------------------------------------
extern "C" void kernel_launch(void* const* d_in, const int* in_sizes, int n_in,
                              void* d_out, int out_size)
{
    const float* node_attrs = (const float*)d_in[0];
    const float* positions  = (const float*)d_in[1];
    const int*   edge_index = (const int*)  d_in[2];
    const float* proj_W     = (const float*)d_in[3];
    const float* emb_in_W   = (const float*)d_in[4];
    const float* emb_in_b   = (const float*)d_in[5];
    const float* edge_W1    = (const float*)d_in[6];
    const float* edge_b1    = (const float*)d_in[7];
    const float* edge_W2    = (const float*)d_in[8];
    const float* edge_b2    = (const float*)d_in[9];
    const float* node_W1    = (const float*)d_in[10];
    const float* node_b1    = (const float*)d_in[11];
    const float* node_W2    = (const float*)d_in[12];
    const float* node_b2    = (const float*)d_in[13];
    const float* coord_W1   = (const float*)d_in[14];
    const float* coord_b1   = (const float*)d_in[15];
    const float* coord_W2   = (const float*)d_in[16];
    const float* lin_W      = (const float*)d_in[19];

    int n = in_sizes[0] / 3;
    int E = in_sizes[2] / 2;

    float* out = (float*)d_out;

    prep_kernel<<<1, 256>>>(edge_W1, edge_W2, edge_b2,
                            coord_W1, coord_b1, coord_W2);          // launch 1
    init_kernel<<<(n + 127) / 128, 128>>>(node_attrs, positions, proj_W,
                                          emb_in_W, emb_in_b,
                                          edge_W1, edge_b1, n);     // launch 2
    count_kernel<<<(E + 255) / 256, 256>>>(edge_index, E);          // launch 3

    int eblocks = (E + ETPB - 1) / ETPB;
    int nblocks = (n + NTPB - 1) / NTPB;

    edge_kernel<0><<<eblocks, ETPB>>>(edge_index, E, positions);    // launch 4
    node_kernel<<<nblocks, NTPB>>>(
        node_W1, node_b1, node_W2, node_b2,
        edge_W1 + H * 68, edge_b1 + H, nullptr, out, n);            // launch 5
    edge_kernel<1><<<eblocks, ETPB>>>(edge_index, E, positions);    // launch 6
    node_kernel<<<nblocks, NTPB>>>(
        node_W1 + H * 2 * H, node_b1 + H, node_W2 + H * H, node_b2 + H,
        nullptr, nullptr, lin_W, out, n);                           // launch 7
}

// round 11
// speedup vs baseline: 2.4177x; 2.4177x over previous
#include <cuda_runtime.h>
#include <cuda_bf16.h>

#define H    32
#define DX   16
#define HQ   16
#define NMAX 50048

typedef unsigned long long u64;
typedef unsigned int u32;
typedef __nv_bfloat162 bf2;

__device__ __align__(16) float g_x[NMAX * DX];
__device__ __align__(16) float g_h[NMAX * H];
__device__ __align__(16) u32 g_A[NMAX * HQ];
__device__ __align__(16) u32 g_B[NMAX * HQ];
__device__ __align__(16) float g_magg[NMAX * H];
__device__ __align__(16) float g_tagg[NMAX * DX];
__device__ float g_cnt[NMAX];
__device__ int g_dummy;

__device__ __forceinline__ float silu_f(float v) {
    return v * (1.0f / (1.0f + __expf(-v)));
}
__device__ __forceinline__ u32 b2u(bf2 v) { return *reinterpret_cast<u32*>(&v); }
__device__ __forceinline__ bf2 u2b(u32 v) { return *reinterpret_cast<bf2*>(&v); }

__device__ __forceinline__ bf2 silu_b(bf2 v) {
    bf2 h = __hmul2(v, __float2bfloat162_rn(0.5f));
    u32 tu;
    u32 hu = b2u(h);
    asm("tanh.approx.bf16x2 %0, %1;" : "=r"(tu) : "r"(hu));
    return __hmul2(h, __hadd2(u2b(tu), __float2bfloat162_rn(1.0f)));
}

__device__ __forceinline__ u64 pack2(float lo, float hi) {
    u64 r; asm("mov.b64 %0, {%1,%2};" : "=l"(r) : "f"(lo), "f"(hi)); return r;
}
__device__ __forceinline__ void unpack2(u64 v, float& lo, float& hi) {
    asm("mov.b64 {%0,%1}, %2;" : "=f"(lo), "=f"(hi) : "l"(v));
}
__device__ __forceinline__ void fma2(u64& d, u64 a, u64 b) {
    asm("fma.rn.f32x2 %0, %1, %2, %0;" : "+l"(d) : "l"(a), "l"(b));
}
__device__ __forceinline__ u64 dup2(float v) {
    u64 r; asm("mov.b64 %0, {%1,%1};" : "=l"(r) : "f"(v)); return r;
}
__device__ __forceinline__ void red_add_v4(float* a, float x, float y, float z, float w) {
    asm volatile("red.global.add.v4.f32 [%0], {%1,%2,%3,%4};"
                 :: "l"(a), "f"(x), "f"(y), "f"(z), "f"(w) : "memory");
}

__global__ __launch_bounds__(128, 4) void init_kernel(
    const float* __restrict__ attrs, const float* __restrict__ pos,
    const float* __restrict__ projW, const float* __restrict__ embW,
    const float* __restrict__ embB, const float* __restrict__ eW1,
    const float* __restrict__ eb1, int n)
{
    __shared__ __align__(16) float sWa[H][H];
    __shared__ __align__(16) float sWb[H][H];
    for (int idx = threadIdx.x; idx < H * H; idx += 128) {
        int j = idx >> 5, k = idx & 31;
        sWa[k][j] = eW1[j * 68 + k];
        sWb[k][j] = eW1[j * 68 + 32 + k];
    }
    __syncthreads();
    int i = blockIdx.x * 128 + threadIdx.x;
    if (i >= n) return;

    float p0 = pos[i*3], p1 = pos[i*3+1], p2 = pos[i*3+2];
    float xv[DX];
#pragma unroll
    for (int j = 0; j < DX; j++)
        xv[j] = projW[j*3]*p0 + projW[j*3+1]*p1 + projW[j*3+2]*p2;
    float4* xo = (float4*)&g_x[i * DX];
#pragma unroll
    for (int q = 0; q < 4; q++)
        xo[q] = make_float4(xv[4*q], xv[4*q+1], xv[4*q+2], xv[4*q+3]);

    float a0 = attrs[i*3], a1 = attrs[i*3+1], a2 = attrs[i*3+2];
    float hv[H];
#pragma unroll
    for (int j = 0; j < H; j++)
        hv[j] = embW[j*3]*a0 + embW[j*3+1]*a1 + embW[j*3+2]*a2 + embB[j];
    float4* ho = (float4*)&g_h[i * H];
#pragma unroll
    for (int q = 0; q < 8; q++)
        ho[q] = make_float4(hv[4*q], hv[4*q+1], hv[4*q+2], hv[4*q+3]);

    float Av[H], Bv[H];
#pragma unroll
    for (int j = 0; j < H; j++) { Av[j] = eb1[j]; Bv[j] = 0.0f; }
#pragma unroll
    for (int k = 0; k < H; k++) {
        float hk = hv[k];
        const float4* wa = (const float4*)&sWa[k][0];
        const float4* wb = (const float4*)&sWb[k][0];
#pragma unroll
        for (int q = 0; q < 8; q++) {
            float4 a = wa[q], b = wb[q];
            Av[4*q] += a.x*hk; Av[4*q+1] += a.y*hk; Av[4*q+2] += a.z*hk; Av[4*q+3] += a.w*hk;
            Bv[4*q] += b.x*hk; Bv[4*q+1] += b.y*hk; Bv[4*q+2] += b.z*hk; Bv[4*q+3] += b.w*hk;
        }
    }
    u32 pa[HQ], pb[HQ];
#pragma unroll
    for (int jq = 0; jq < HQ; jq++) {
        pa[jq] = b2u(__floats2bfloat162_rn(Av[2*jq], Av[2*jq+1]));
        pb[jq] = b2u(__floats2bfloat162_rn(Bv[2*jq], Bv[2*jq+1]));
    }
    uint4* Ao = (uint4*)&g_A[i * HQ];
    uint4* Bo = (uint4*)&g_B[i * HQ];
#pragma unroll
    for (int q = 0; q < 4; q++) {
        Ao[q] = make_uint4(pa[4*q], pa[4*q+1], pa[4*q+2], pa[4*q+3]);
        Bo[q] = make_uint4(pb[4*q], pb[4*q+1], pb[4*q+2], pb[4*q+3]);
    }

    const float4 z4 = make_float4(0.f, 0.f, 0.f, 0.f);
    float4* mz = (float4*)&g_magg[i * H];
    float4* tz = (float4*)&g_tagg[i * DX];
#pragma unroll
    for (int q = 0; q < 8; q++) mz[q] = z4;
#pragma unroll
    for (int q = 0; q < 4; q++) tz[q] = z4;
    g_cnt[i] = 0.0f;
}

__global__ void count_kernel(const int* __restrict__ ei, int E)
{
    int e = blockIdx.x * blockDim.x + threadIdx.x;
    if (e < E) atomicAdd(&g_cnt[ei[e]], 1.0f);
}

__global__ void nop_kernel() { if (blockIdx.x == 1u << 30) g_dummy = 1; }

#define ETPB 128

__global__ __launch_bounds__(ETPB) void edge_kernel(
    const int* __restrict__ ei, int E,
    const float* __restrict__ pos,
    const float* __restrict__ W1,
    const float* __restrict__ W2,
    const float* __restrict__ b2,
    const float* __restrict__ cW1,
    const float* __restrict__ cb1,
    const float* __restrict__ cW2)
{
    __shared__ __align__(16) u32 s_W2t[H][HQ];
    __shared__ __align__(16) u32 s_cW1t[H][HQ];
    __shared__ __align__(16) u64 s_wr2[HQ];
    __shared__ __align__(16) u64 s_we2[3][HQ];
    __shared__ u32 s_b2b[HQ], s_cb1b[HQ], s_cw2b[HQ];

    for (int idx = threadIdx.x; idx < H * HQ; idx += ETPB) {
        int k = idx >> 4, jq = idx & 15;
        s_W2t[k][jq]  = b2u(__floats2bfloat162_rn(W2[(2*jq)*H+k],  W2[(2*jq+1)*H+k]));
        s_cW1t[k][jq] = b2u(__floats2bfloat162_rn(cW1[(2*jq)*H+k], cW1[(2*jq+1)*H+k]));
    }
    if (threadIdx.x < HQ) {
        int jq = threadIdx.x;
        s_wr2[jq]    = pack2(W1[(2*jq)*68+64], W1[(2*jq+1)*68+64]);
        s_we2[0][jq] = pack2(W1[(2*jq)*68+65], W1[(2*jq+1)*68+65]);
        s_we2[1][jq] = pack2(W1[(2*jq)*68+66], W1[(2*jq+1)*68+66]);
        s_we2[2][jq] = pack2(W1[(2*jq)*68+67], W1[(2*jq+1)*68+67]);
        s_b2b[jq]  = b2u(__floats2bfloat162_rn(b2[2*jq],  b2[2*jq+1]));
        s_cb1b[jq] = b2u(__floats2bfloat162_rn(cb1[2*jq], cb1[2*jq+1]));
        s_cw2b[jq] = b2u(__floats2bfloat162_rn(cW2[2*jq], cW2[2*jq+1]));
    }
    __syncthreads();

    int e = blockIdx.x * ETPB + threadIdx.x;
    if (e >= E) return;

    int row = ei[e];
    int col = ei[E + e];

    float ea0 = pos[row*3]   - pos[col*3];
    float ea1 = pos[row*3+1] - pos[col*3+1];
    float ea2 = pos[row*3+2] - pos[col*3+2];

    float cd[DX];
    const float4* xr = (const float4*)&g_x[row * DX];
    const float4* xc = (const float4*)&g_x[col * DX];
    float radial = 0.0f;
#pragma unroll
    for (int q = 0; q < 4; q++) {
        float4 a = xr[q], b = xc[q];
        float d0 = a.x-b.x, d1 = a.y-b.y, d2 = a.z-b.z, d3 = a.w-b.w;
        cd[4*q] = d0; cd[4*q+1] = d1; cd[4*q+2] = d2; cd[4*q+3] = d3;
        radial += d0*d0 + d1*d1 + d2*d2 + d3*d3;
    }

    // layer 1: fp32 f32x2, A/B gathered as bf16
    bf2 a_bf[HQ];
    {
        u64 acc2[HQ];
        const uint4* Ar = (const uint4*)&g_A[row * HQ];
        const uint4* Bc = (const uint4*)&g_B[col * HQ];
#pragma unroll
        for (int q = 0; q < 4; q++) {
            uint4 a4 = Ar[q], b4 = Bc[q];
            const u32* ap = (const u32*)&a4;
            const u32* bp = (const u32*)&b4;
#pragma unroll
            for (int r = 0; r < 4; r++) {
                float2 af = __bfloat1622float2(u2b(ap[r]));
                float2 bf = __bfloat1622float2(u2b(bp[r]));
                acc2[4*q + r] = pack2(af.x + bf.x, af.y + bf.y);
            }
        }
        u64 rad2 = dup2(radial);
        u64 e02 = dup2(ea0), e12 = dup2(ea1), e22 = dup2(ea2);
#pragma unroll
        for (int jq = 0; jq < HQ; jq++) {
            fma2(acc2[jq], s_wr2[jq], rad2);
            fma2(acc2[jq], s_we2[0][jq], e02);
            fma2(acc2[jq], s_we2[1][jq], e12);
            fma2(acc2[jq], s_we2[2][jq], e22);
        }
#pragma unroll
        for (int jq = 0; jq < HQ; jq++) {
            float lo, hi;
            unpack2(acc2[jq], lo, hi);
            a_bf[jq] = silu_b(__floats2bfloat162_rn(lo, hi));
        }
    }

    // layer 2: bf16 HFMA2
    bf2 ms[HQ];
    {
        bf2 m2[HQ];
#pragma unroll
        for (int jq = 0; jq < HQ; jq++) m2[jq] = u2b(s_b2b[jq]);
#pragma unroll
        for (int k = 0; k < H; k++) {
            bf2 mk = (k & 1) ? __high2bfloat162(a_bf[k >> 1]) : __low2bfloat162(a_bf[k >> 1]);
            const uint4* w4 = (const uint4*)&s_W2t[k][0];
#pragma unroll
            for (int q = 0; q < 4; q++) {
                uint4 w = w4[q];
                m2[4*q]   = __hfma2(u2b(w.x), mk, m2[4*q]);
                m2[4*q+1] = __hfma2(u2b(w.y), mk, m2[4*q+1]);
                m2[4*q+2] = __hfma2(u2b(w.z), mk, m2[4*q+2]);
                m2[4*q+3] = __hfma2(u2b(w.w), mk, m2[4*q+3]);
            }
        }
#pragma unroll
        for (int jq = 0; jq < HQ; jq++) ms[jq] = silu_b(m2[jq]);
    }

    // coord head: bf16 HFMA2, fp32 reduce
    float cm = 0.0f;
    {
        bf2 c2[HQ];
#pragma unroll
        for (int jq = 0; jq < HQ; jq++) c2[jq] = u2b(s_cb1b[jq]);
#pragma unroll
        for (int k = 0; k < H; k++) {
            bf2 mk = (k & 1) ? __high2bfloat162(ms[k >> 1]) : __low2bfloat162(ms[k >> 1]);
            const uint4* w4 = (const uint4*)&s_cW1t[k][0];
#pragma unroll
            for (int q = 0; q < 4; q++) {
                uint4 w = w4[q];
                c2[4*q]   = __hfma2(u2b(w.x), mk, c2[4*q]);
                c2[4*q+1] = __hfma2(u2b(w.y), mk, c2[4*q+1]);
                c2[4*q+2] = __hfma2(u2b(w.z), mk, c2[4*q+2]);
                c2[4*q+3] = __hfma2(u2b(w.w), mk, c2[4*q+3]);
            }
        }
#pragma unroll
        for (int jq = 0; jq < HQ; jq++) {
            bf2 p = __hmul2(u2b(s_cw2b[jq]), silu_b(c2[jq]));
            float2 pf = __bfloat1622float2(p);
            cm += pf.x + pf.y;
        }
    }

    float* mago = &g_magg[row * H];
#pragma unroll
    for (int q = 0; q < 8; q++) {
        float2 f0 = __bfloat1622float2(ms[2*q]);
        float2 f1 = __bfloat1622float2(ms[2*q+1]);
        red_add_v4(mago + 4*q, f0.x, f0.y, f1.x, f1.y);
    }
    float* tago = &g_tagg[row * DX];
#pragma unroll
    for (int q = 0; q < 4; q++)
        red_add_v4(tago + 4*q, cd[4*q]*cm, cd[4*q+1]*cm, cd[4*q+2]*cm, cd[4*q+3]*cm);
}

#define NTPB 128

__global__ __launch_bounds__(NTPB, 4) void node_kernel(
    const float* __restrict__ nW1, const float* __restrict__ nb1,
    const float* __restrict__ nW2, const float* __restrict__ nb2,
    const float* __restrict__ eW1n, const float* __restrict__ eb1n,
    const float* __restrict__ linW, float* __restrict__ out, int n)
{
    __shared__ __align__(16) float sN1t[2 * H][H];
    __shared__ __align__(16) float sN2t[H][H];
    __shared__ __align__(16) float sEAt[H][H];
    __shared__ __align__(16) float sEBt[H][H];

    int i = blockIdx.x * NTPB + threadIdx.x;
    bool active = (i < n);

    float cnt = 0.f;
    float4 xr[4], tr[4], hr[8], mr[8];
    if (active) {
        cnt = g_cnt[i];
        const float4* xp = (const float4*)&g_x[i * DX];
        const float4* tp = (const float4*)&g_tagg[i * DX];
        const float4* hp = (const float4*)&g_h[i * H];
        const float4* mp = (const float4*)&g_magg[i * H];
#pragma unroll
        for (int q = 0; q < 4; q++) { xr[q] = xp[q]; tr[q] = tp[q]; }
#pragma unroll
        for (int q = 0; q < 8; q++) { hr[q] = hp[q]; mr[q] = mp[q]; }
    }

    for (int idx = threadIdx.x; idx < H * 2 * H; idx += NTPB) {
        int j = idx >> 6, k = idx & 63;
        sN1t[k][j] = nW1[idx];
    }
    for (int idx = threadIdx.x; idx < H * H; idx += NTPB) {
        int j = idx >> 5, k = idx & 31;
        sN2t[k][j] = nW2[idx];
        if (eW1n) {
            sEAt[k][j] = eW1n[j * 68 + k];
            sEBt[k][j] = eW1n[j * 68 + 32 + k];
        }
    }
    __syncthreads();

    if (!active) return;

    float inv = 1.0f / fmaxf(cnt, 1.0f);
    const float4 z4 = make_float4(0.f, 0.f, 0.f, 0.f);

    float xv[DX];
    float4* xp = (float4*)&g_x[i * DX];
    float4* tp = (float4*)&g_tagg[i * DX];
#pragma unroll
    for (int q = 0; q < 4; q++) {
        xv[4*q]   = xr[q].x + tr[q].x * inv;
        xv[4*q+1] = xr[q].y + tr[q].y * inv;
        xv[4*q+2] = xr[q].z + tr[q].z * inv;
        xv[4*q+3] = xr[q].w + tr[q].w * inv;
        xp[q] = make_float4(xv[4*q], xv[4*q+1], xv[4*q+2], xv[4*q+3]);
        tp[q] = z4;
    }

    float hv[H], mg[H];
    float4* mp = (float4*)&g_magg[i * H];
#pragma unroll
    for (int q = 0; q < 8; q++) {
        hv[4*q] = hr[q].x; hv[4*q+1] = hr[q].y; hv[4*q+2] = hr[q].z; hv[4*q+3] = hr[q].w;
        mg[4*q] = mr[q].x; mg[4*q+1] = mr[q].y; mg[4*q+2] = mr[q].z; mg[4*q+3] = mr[q].w;
        mp[q] = z4;
    }

    float u[H];
#pragma unroll
    for (int j = 0; j < H; j++) u[j] = nb1[j];
#pragma unroll
    for (int k = 0; k < H; k++) {
        float v = hv[k];
        const float4* w4 = (const float4*)&sN1t[k][0];
#pragma unroll
        for (int q = 0; q < 8; q++) {
            float4 w = w4[q];
            u[4*q] += w.x*v; u[4*q+1] += w.y*v; u[4*q+2] += w.z*v; u[4*q+3] += w.w*v;
        }
    }
#pragma unroll
    for (int k = 0; k < H; k++) {
        float v = mg[k];
        const float4* w4 = (const float4*)&sN1t[H + k][0];
#pragma unroll
        for (int q = 0; q < 8; q++) {
            float4 w = w4[q];
            u[4*q] += w.x*v; u[4*q+1] += w.y*v; u[4*q+2] += w.z*v; u[4*q+3] += w.w*v;
        }
    }
#pragma unroll
    for (int j = 0; j < H; j++) u[j] = silu_f(u[j]);

    float hn[H];
#pragma unroll
    for (int j = 0; j < H; j++) hn[j] = nb2[j];
#pragma unroll
    for (int k = 0; k < H; k++) {
        float v = u[k];
        const float4* w4 = (const float4*)&sN2t[k][0];
#pragma unroll
        for (int q = 0; q < 8; q++) {
            float4 w = w4[q];
            hn[4*q] += w.x*v; hn[4*q+1] += w.y*v; hn[4*q+2] += w.z*v; hn[4*q+3] += w.w*v;
        }
    }
#pragma unroll
    for (int j = 0; j < H; j++) hn[j] += hv[j];
    float4* hp = (float4*)&g_h[i * H];
#pragma unroll
    for (int q = 0; q < 8; q++)
        hp[q] = make_float4(hn[4*q], hn[4*q+1], hn[4*q+2], hn[4*q+3]);

    if (eW1n) {
        float Av[H], Bv[H];
#pragma unroll
        for (int j = 0; j < H; j++) { Av[j] = eb1n[j]; Bv[j] = 0.0f; }
#pragma unroll
        for (int k = 0; k < H; k++) {
            float v = hn[k];
            const float4* wa = (const float4*)&sEAt[k][0];
            const float4* wb = (const float4*)&sEBt[k][0];
#pragma unroll
            for (int q = 0; q < 8; q++) {
                float4 a = wa[q], b = wb[q];
                Av[4*q] += a.x*v; Av[4*q+1] += a.y*v; Av[4*q+2] += a.z*v; Av[4*q+3] += a.w*v;
                Bv[4*q] += b.x*v; Bv[4*q+1] += b.y*v; Bv[4*q+2] += b.z*v; Bv[4*q+3] += b.w*v;
            }
        }
        u32 pa[HQ], pb[HQ];
#pragma unroll
        for (int jq = 0; jq < HQ; jq++) {
            pa[jq] = b2u(__floats2bfloat162_rn(Av[2*jq], Av[2*jq+1]));
            pb[jq] = b2u(__floats2bfloat162_rn(Bv[2*jq], Bv[2*jq+1]));
        }
        uint4* Ao = (uint4*)&g_A[i * HQ];
        uint4* Bo = (uint4*)&g_B[i * HQ];
#pragma unroll
        for (int q = 0; q < 4; q++) {
            Ao[q] = make_uint4(pa[4*q], pa[4*q+1], pa[4*q+2], pa[4*q+3]);
            Bo[q] = make_uint4(pb[4*q], pb[4*q+1], pb[4*q+2], pb[4*q+3]);
        }
    }

    if (linW) {
#pragma unroll
        for (int c = 0; c < 3; c++) {
            float acc = 0.0f;
#pragma unroll
            for (int k = 0; k < DX; k++) acc += linW[c * DX + k] * xv[k];
            out[i * 3 + c] = acc;
        }
    }
}

extern "C" void kernel_launch(void* const* d_in, const int* in_sizes, int n_in,
                              void* d_out, int out_size)
{
    const float* node_attrs = (const float*)d_in[0];
    const float* positions  = (const float*)d_in[1];
    const int*   edge_index = (const int*)  d_in[2];
    const float* proj_W     = (const float*)d_in[3];
    const float* emb_in_W   = (const float*)d_in[4];
    const float* emb_in_b   = (const float*)d_in[5];
    const float* edge_W1    = (const float*)d_in[6];
    const float* edge_b1    = (const float*)d_in[7];
    const float* edge_W2    = (const float*)d_in[8];
    const float* edge_b2    = (const float*)d_in[9];
    const float* node_W1    = (const float*)d_in[10];
    const float* node_b1    = (const float*)d_in[11];
    const float* node_W2    = (const float*)d_in[12];
    const float* node_b2    = (const float*)d_in[13];
    const float* coord_W1   = (const float*)d_in[14];
    const float* coord_b1   = (const float*)d_in[15];
    const float* coord_W2   = (const float*)d_in[16];
    const float* lin_W      = (const float*)d_in[19];

    int n = in_sizes[0] / 3;
    int E = in_sizes[2] / 2;
    float* out = (float*)d_out;

    init_kernel<<<(n + 127) / 128, 128>>>(node_attrs, positions, proj_W,
                                          emb_in_W, emb_in_b, edge_W1, edge_b1, n);
    count_kernel<<<(E + 255) / 256, 256>>>(edge_index, E);
    nop_kernel<<<1, 32>>>();

    int eblocks = (E + ETPB - 1) / ETPB;
    int nblocks = (n + NTPB - 1) / NTPB;

    for (int l = 0; l < 2; l++) {
        edge_kernel<<<eblocks, ETPB>>>(
            edge_index, E, positions,
            edge_W1 + l * H * 68,
            edge_W2 + l * H * H, edge_b2 + l * H,
            coord_W1 + l * H * H, coord_b1 + l * H,
            coord_W2 + l * H);
        node_kernel<<<nblocks, NTPB>>>(
            node_W1 + l * H * 2 * H, node_b1 + l * H,
            node_W2 + l * H * H,     node_b2 + l * H,
            (l == 0) ? edge_W1 + H * 68 : nullptr,
            (l == 0) ? edge_b1 + H      : nullptr,
            (l == 1) ? lin_W            : nullptr,
            out, n);
    }
}

// round 12
// speedup vs baseline: 2.7302x; 1.1292x over previous
#include <cuda_runtime.h>
#include <cuda_bf16.h>

#define H    32
#define DX   16
#define HQ   16
#define NMAX 50048

typedef unsigned long long u64;
typedef unsigned int u32;
typedef __nv_bfloat162 bf2;

__device__ __align__(16) float g_x[NMAX * DX];
__device__ __align__(16) float g_h[NMAX * H];
__device__ __align__(16) u32 g_A[NMAX * HQ];
__device__ __align__(16) u32 g_B[NMAX * HQ];
__device__ __align__(16) float g_magg[NMAX * H];
__device__ __align__(16) float g_tagg[NMAX * DX];
__device__ float g_cnt[NMAX];
__device__ int g_dummy;

__device__ __forceinline__ float silu_f(float v) {
    return v * (1.0f / (1.0f + __expf(-v)));
}
__device__ __forceinline__ u32 b2u(bf2 v) { return *reinterpret_cast<u32*>(&v); }
__device__ __forceinline__ bf2 u2b(u32 v) { return *reinterpret_cast<bf2*>(&v); }

__device__ __forceinline__ bf2 silu_b(bf2 v) {
    bf2 h = __hmul2(v, __float2bfloat162_rn(0.5f));
    u32 tu;
    u32 hu = b2u(h);
    asm("tanh.approx.bf16x2 %0, %1;" : "=r"(tu) : "r"(hu));
    return __hmul2(h, __hadd2(u2b(tu), __float2bfloat162_rn(1.0f)));
}

__device__ __forceinline__ u64 pack2(float lo, float hi) {
    u64 r; asm("mov.b64 %0, {%1,%2};" : "=l"(r) : "f"(lo), "f"(hi)); return r;
}
__device__ __forceinline__ void unpack2(u64 v, float& lo, float& hi) {
    asm("mov.b64 {%0,%1}, %2;" : "=f"(lo), "=f"(hi) : "l"(v));
}
__device__ __forceinline__ void fma2(u64& d, u64 a, u64 b) {
    asm("fma.rn.f32x2 %0, %1, %2, %0;" : "+l"(d) : "l"(a), "l"(b));
}
__device__ __forceinline__ u64 dup2(float v) {
    u64 r; asm("mov.b64 %0, {%1,%1};" : "=l"(r) : "f"(v)); return r;
}
__device__ __forceinline__ void red_add_v4(float* a, float x, float y, float z, float w) {
    asm volatile("red.global.add.v4.f32 [%0], {%1,%2,%3,%4};"
                 :: "l"(a), "f"(x), "f"(y), "f"(z), "f"(w) : "memory");
}

// ---------------------------------------------------------------------------
__global__ __launch_bounds__(128, 4) void init_kernel(
    const float* __restrict__ attrs, const float* __restrict__ pos,
    const float* __restrict__ projW, const float* __restrict__ embW,
    const float* __restrict__ embB, const float* __restrict__ eW1,
    const float* __restrict__ eb1, int n)
{
    __shared__ __align__(16) float sWa[H][H];
    __shared__ __align__(16) float sWb[H][H];
    for (int idx = threadIdx.x; idx < H * H; idx += 128) {
        int j = idx >> 5, k = idx & 31;
        sWa[k][j] = eW1[j * 68 + k];
        sWb[k][j] = eW1[j * 68 + 32 + k];
    }
    __syncthreads();
    int i = blockIdx.x * 128 + threadIdx.x;
    if (i >= n) return;

    float p0 = pos[i*3], p1 = pos[i*3+1], p2 = pos[i*3+2];
    float xv[DX];
#pragma unroll
    for (int j = 0; j < DX; j++)
        xv[j] = projW[j*3]*p0 + projW[j*3+1]*p1 + projW[j*3+2]*p2;
    float4* xo = (float4*)&g_x[i * DX];
#pragma unroll
    for (int q = 0; q < 4; q++)
        xo[q] = make_float4(xv[4*q], xv[4*q+1], xv[4*q+2], xv[4*q+3]);

    float a0 = attrs[i*3], a1 = attrs[i*3+1], a2 = attrs[i*3+2];
    float hv[H];
#pragma unroll
    for (int j = 0; j < H; j++)
        hv[j] = embW[j*3]*a0 + embW[j*3+1]*a1 + embW[j*3+2]*a2 + embB[j];
    float4* ho = (float4*)&g_h[i * H];
#pragma unroll
    for (int q = 0; q < 8; q++)
        ho[q] = make_float4(hv[4*q], hv[4*q+1], hv[4*q+2], hv[4*q+3]);

    float Av[H], Bv[H];
#pragma unroll
    for (int j = 0; j < H; j++) { Av[j] = eb1[j]; Bv[j] = 0.0f; }
#pragma unroll
    for (int k = 0; k < H; k++) {
        float hk = hv[k];
        const float4* wa = (const float4*)&sWa[k][0];
        const float4* wb = (const float4*)&sWb[k][0];
#pragma unroll
        for (int q = 0; q < 8; q++) {
            float4 a = wa[q], b = wb[q];
            Av[4*q] += a.x*hk; Av[4*q+1] += a.y*hk; Av[4*q+2] += a.z*hk; Av[4*q+3] += a.w*hk;
            Bv[4*q] += b.x*hk; Bv[4*q+1] += b.y*hk; Bv[4*q+2] += b.z*hk; Bv[4*q+3] += b.w*hk;
        }
    }
    u32 pa[HQ], pb[HQ];
#pragma unroll
    for (int jq = 0; jq < HQ; jq++) {
        pa[jq] = b2u(__floats2bfloat162_rn(Av[2*jq], Av[2*jq+1]));
        pb[jq] = b2u(__floats2bfloat162_rn(Bv[2*jq], Bv[2*jq+1]));
    }
    uint4* Ao = (uint4*)&g_A[i * HQ];
    uint4* Bo = (uint4*)&g_B[i * HQ];
#pragma unroll
    for (int q = 0; q < 4; q++) {
        Ao[q] = make_uint4(pa[4*q], pa[4*q+1], pa[4*q+2], pa[4*q+3]);
        Bo[q] = make_uint4(pb[4*q], pb[4*q+1], pb[4*q+2], pb[4*q+3]);
    }

    const float4 z4 = make_float4(0.f, 0.f, 0.f, 0.f);
    float4* mz = (float4*)&g_magg[i * H];
    float4* tz = (float4*)&g_tagg[i * DX];
#pragma unroll
    for (int q = 0; q < 8; q++) mz[q] = z4;
#pragma unroll
    for (int q = 0; q < 4; q++) tz[q] = z4;
    g_cnt[i] = 0.0f;
}

__global__ void count_kernel(const int* __restrict__ ei, int E)
{
    int e = blockIdx.x * blockDim.x + threadIdx.x;
    if (e < E) atomicAdd(&g_cnt[ei[e]], 1.0f);
}

__global__ void nop_kernel() { if (blockIdx.x == 1u << 30) g_dummy = 1; }

// ---------------------------------------------------------------------------
// edge kernel: T=2 edges/thread, bf16 MLP, shared weight LDS across edges
// ---------------------------------------------------------------------------
#define ETPB 128

__global__ __launch_bounds__(ETPB, 3) void edge_kernel(
    const int* __restrict__ ei, int E,
    const float* __restrict__ pos,
    const float* __restrict__ W1,
    const float* __restrict__ W2,
    const float* __restrict__ b2,
    const float* __restrict__ cW1,
    const float* __restrict__ cb1,
    const float* __restrict__ cW2)
{
    __shared__ __align__(16) u32 s_W2t[H][HQ];
    __shared__ __align__(16) u32 s_cW1t[H][HQ];
    __shared__ __align__(16) u64 s_wr2[HQ];
    __shared__ __align__(16) u64 s_we2[3][HQ];
    __shared__ u32 s_b2b[HQ], s_cb1b[HQ], s_cw2b[HQ];

    for (int idx = threadIdx.x; idx < H * HQ; idx += ETPB) {
        int k = idx >> 4, jq = idx & 15;
        s_W2t[k][jq]  = b2u(__floats2bfloat162_rn(W2[(2*jq)*H+k],  W2[(2*jq+1)*H+k]));
        s_cW1t[k][jq] = b2u(__floats2bfloat162_rn(cW1[(2*jq)*H+k], cW1[(2*jq+1)*H+k]));
    }
    if (threadIdx.x < HQ) {
        int jq = threadIdx.x;
        s_wr2[jq]    = pack2(W1[(2*jq)*68+64], W1[(2*jq+1)*68+64]);
        s_we2[0][jq] = pack2(W1[(2*jq)*68+65], W1[(2*jq+1)*68+65]);
        s_we2[1][jq] = pack2(W1[(2*jq)*68+66], W1[(2*jq+1)*68+66]);
        s_we2[2][jq] = pack2(W1[(2*jq)*68+67], W1[(2*jq+1)*68+67]);
        s_b2b[jq]  = b2u(__floats2bfloat162_rn(b2[2*jq],  b2[2*jq+1]));
        s_cb1b[jq] = b2u(__floats2bfloat162_rn(cb1[2*jq], cb1[2*jq+1]));
        s_cw2b[jq] = b2u(__floats2bfloat162_rn(cW2[2*jq], cW2[2*jq+1]));
    }
    __syncthreads();

    int e0 = blockIdx.x * (2 * ETPB) + threadIdx.x;
    if (e0 >= E) return;
    int e1 = e0 + ETPB;
    bool v1 = (e1 < E);
    int e1c = v1 ? e1 : e0;

    int row0 = ei[e0],  col0 = ei[E + e0];
    int row1 = ei[e1c], col1 = ei[E + e1c];

    float ea00 = pos[row0*3]   - pos[col0*3];
    float ea01 = pos[row0*3+1] - pos[col0*3+1];
    float ea02 = pos[row0*3+2] - pos[col0*3+2];
    float ea10 = pos[row1*3]   - pos[col1*3];
    float ea11 = pos[row1*3+1] - pos[col1*3+1];
    float ea12 = pos[row1*3+2] - pos[col1*3+2];

    // cd stored as bf16 pairs to bound registers (trans path is 1e-3 damped)
    bf2 cd0[8], cd1[8];
    float rad0 = 0.0f, rad1 = 0.0f;
    {
        const float4* xr0 = (const float4*)&g_x[row0 * DX];
        const float4* xc0 = (const float4*)&g_x[col0 * DX];
        const float4* xr1 = (const float4*)&g_x[row1 * DX];
        const float4* xc1 = (const float4*)&g_x[col1 * DX];
#pragma unroll
        for (int q = 0; q < 4; q++) {
            float4 a = xr0[q], b = xc0[q];
            float d0 = a.x-b.x, d1 = a.y-b.y, d2 = a.z-b.z, d3 = a.w-b.w;
            cd0[2*q]   = __floats2bfloat162_rn(d0, d1);
            cd0[2*q+1] = __floats2bfloat162_rn(d2, d3);
            rad0 += d0*d0 + d1*d1 + d2*d2 + d3*d3;
            float4 c = xr1[q], d = xc1[q];
            float f0 = c.x-d.x, f1 = c.y-d.y, f2 = c.z-d.z, f3 = c.w-d.w;
            cd1[2*q]   = __floats2bfloat162_rn(f0, f1);
            cd1[2*q+1] = __floats2bfloat162_rn(f2, f3);
            rad1 += f0*f0 + f1*f1 + f2*f2 + f3*f3;
        }
    }

    // ---- layer 1 per edge (transient f32x2 accumulators) ------------------
    bf2 a0_bf[HQ], a1_bf[HQ];
#pragma unroll
    for (int ed = 0; ed < 2; ed++) {
        int row = ed ? row1 : row0;
        int col = ed ? col1 : col0;
        float rad = ed ? rad1 : rad0;
        float ex = ed ? ea10 : ea00;
        float ey = ed ? ea11 : ea01;
        float ez = ed ? ea12 : ea02;
        u64 acc2[HQ];
        const uint4* Ar = (const uint4*)&g_A[row * HQ];
        const uint4* Bc = (const uint4*)&g_B[col * HQ];
#pragma unroll
        for (int q = 0; q < 4; q++) {
            uint4 a4 = Ar[q], b4 = Bc[q];
            const u32* ap = (const u32*)&a4;
            const u32* bp = (const u32*)&b4;
#pragma unroll
            for (int r = 0; r < 4; r++) {
                float2 af = __bfloat1622float2(u2b(ap[r]));
                float2 bf = __bfloat1622float2(u2b(bp[r]));
                acc2[4*q + r] = pack2(af.x + bf.x, af.y + bf.y);
            }
        }
        u64 rad2 = dup2(rad);
        u64 e02 = dup2(ex), e12 = dup2(ey), e22 = dup2(ez);
#pragma unroll
        for (int jq = 0; jq < HQ; jq++) {
            fma2(acc2[jq], s_wr2[jq], rad2);
            fma2(acc2[jq], s_we2[0][jq], e02);
            fma2(acc2[jq], s_we2[1][jq], e12);
            fma2(acc2[jq], s_we2[2][jq], e22);
        }
#pragma unroll
        for (int jq = 0; jq < HQ; jq++) {
            float lo, hi;
            unpack2(acc2[jq], lo, hi);
            bf2 s = silu_b(__floats2bfloat162_rn(lo, hi));
            if (ed) a1_bf[jq] = s; else a0_bf[jq] = s;
        }
    }

    // ---- layer 2: shared weight loads --------------------------------------
    bf2 ms0[HQ], ms1[HQ];
    {
        bf2 m2a[HQ], m2b[HQ];
#pragma unroll
        for (int jq = 0; jq < HQ; jq++) { m2a[jq] = u2b(s_b2b[jq]); m2b[jq] = u2b(s_b2b[jq]); }
#pragma unroll
        for (int k = 0; k < H; k++) {
            bf2 mk0 = (k & 1) ? __high2bfloat162(a0_bf[k >> 1]) : __low2bfloat162(a0_bf[k >> 1]);
            bf2 mk1 = (k & 1) ? __high2bfloat162(a1_bf[k >> 1]) : __low2bfloat162(a1_bf[k >> 1]);
            const uint4* w4 = (const uint4*)&s_W2t[k][0];
#pragma unroll
            for (int q = 0; q < 4; q++) {
                uint4 w = w4[q];
                m2a[4*q]   = __hfma2(u2b(w.x), mk0, m2a[4*q]);
                m2a[4*q+1] = __hfma2(u2b(w.y), mk0, m2a[4*q+1]);
                m2a[4*q+2] = __hfma2(u2b(w.z), mk0, m2a[4*q+2]);
                m2a[4*q+3] = __hfma2(u2b(w.w), mk0, m2a[4*q+3]);
                m2b[4*q]   = __hfma2(u2b(w.x), mk1, m2b[4*q]);
                m2b[4*q+1] = __hfma2(u2b(w.y), mk1, m2b[4*q+1]);
                m2b[4*q+2] = __hfma2(u2b(w.z), mk1, m2b[4*q+2]);
                m2b[4*q+3] = __hfma2(u2b(w.w), mk1, m2b[4*q+3]);
            }
        }
#pragma unroll
        for (int jq = 0; jq < HQ; jq++) {
            ms0[jq] = silu_b(m2a[jq]);
            ms1[jq] = silu_b(m2b[jq]);
        }
    }

    // ---- coord head: shared weight loads ------------------------------------
    float cm0 = 0.0f, cm1 = 0.0f;
    {
        bf2 c2a[HQ], c2b[HQ];
#pragma unroll
        for (int jq = 0; jq < HQ; jq++) { c2a[jq] = u2b(s_cb1b[jq]); c2b[jq] = u2b(s_cb1b[jq]); }
#pragma unroll
        for (int k = 0; k < H; k++) {
            bf2 mk0 = (k & 1) ? __high2bfloat162(ms0[k >> 1]) : __low2bfloat162(ms0[k >> 1]);
            bf2 mk1 = (k & 1) ? __high2bfloat162(ms1[k >> 1]) : __low2bfloat162(ms1[k >> 1]);
            const uint4* w4 = (const uint4*)&s_cW1t[k][0];
#pragma unroll
            for (int q = 0; q < 4; q++) {
                uint4 w = w4[q];
                c2a[4*q]   = __hfma2(u2b(w.x), mk0, c2a[4*q]);
                c2a[4*q+1] = __hfma2(u2b(w.y), mk0, c2a[4*q+1]);
                c2a[4*q+2] = __hfma2(u2b(w.z), mk0, c2a[4*q+2]);
                c2a[4*q+3] = __hfma2(u2b(w.w), mk0, c2a[4*q+3]);
                c2b[4*q]   = __hfma2(u2b(w.x), mk1, c2b[4*q]);
                c2b[4*q+1] = __hfma2(u2b(w.y), mk1, c2b[4*q+1]);
                c2b[4*q+2] = __hfma2(u2b(w.z), mk1, c2b[4*q+2]);
                c2b[4*q+3] = __hfma2(u2b(w.w), mk1, c2b[4*q+3]);
            }
        }
#pragma unroll
        for (int jq = 0; jq < HQ; jq++) {
            bf2 cw = u2b(s_cw2b[jq]);
            float2 pa = __bfloat1622float2(__hmul2(cw, silu_b(c2a[jq])));
            float2 pb = __bfloat1622float2(__hmul2(cw, silu_b(c2b[jq])));
            cm0 += pa.x + pa.y;
            cm1 += pb.x + pb.y;
        }
    }

    // ---- scatters -------------------------------------------------------------
    {
        float* mago = &g_magg[row0 * H];
#pragma unroll
        for (int q = 0; q < 8; q++) {
            float2 f0 = __bfloat1622float2(ms0[2*q]);
            float2 f1 = __bfloat1622float2(ms0[2*q+1]);
            red_add_v4(mago + 4*q, f0.x, f0.y, f1.x, f1.y);
        }
        float* tago = &g_tagg[row0 * DX];
#pragma unroll
        for (int q = 0; q < 4; q++) {
            float2 d0 = __bfloat1622float2(cd0[2*q]);
            float2 d1 = __bfloat1622float2(cd0[2*q+1]);
            red_add_v4(tago + 4*q, d0.x*cm0, d0.y*cm0, d1.x*cm0, d1.y*cm0);
        }
    }
    if (v1) {
        float* mago = &g_magg[row1 * H];
#pragma unroll
        for (int q = 0; q < 8; q++) {
            float2 f0 = __bfloat1622float2(ms1[2*q]);
            float2 f1 = __bfloat1622float2(ms1[2*q+1]);
            red_add_v4(mago + 4*q, f0.x, f0.y, f1.x, f1.y);
        }
        float* tago = &g_tagg[row1 * DX];
#pragma unroll
        for (int q = 0; q < 4; q++) {
            float2 d0 = __bfloat1622float2(cd1[2*q]);
            float2 d1 = __bfloat1622float2(cd1[2*q+1]);
            red_add_v4(tago + 4*q, d0.x*cm1, d0.y*cm1, d1.x*cm1, d1.y*cm1);
        }
    }
}

// ---------------------------------------------------------------------------
#define NTPB 128

__global__ __launch_bounds__(NTPB, 4) void node_kernel(
    const float* __restrict__ nW1, const float* __restrict__ nb1,
    const float* __restrict__ nW2, const float* __restrict__ nb2,
    const float* __restrict__ eW1n, const float* __restrict__ eb1n,
    const float* __restrict__ linW, float* __restrict__ out, int n)
{
    __shared__ __align__(16) float sN1t[2 * H][H];
    __shared__ __align__(16) float sN2t[H][H];
    __shared__ __align__(16) float sEAt[H][H];
    __shared__ __align__(16) float sEBt[H][H];

    int i = blockIdx.x * NTPB + threadIdx.x;
    bool active = (i < n);

    float cnt = 0.f;
    float4 xr[4], tr[4], hr[8], mr[8];
    if (active) {
        cnt = g_cnt[i];
        const float4* xp = (const float4*)&g_x[i * DX];
        const float4* tp = (const float4*)&g_tagg[i * DX];
        const float4* hp = (const float4*)&g_h[i * H];
        const float4* mp = (const float4*)&g_magg[i * H];
#pragma unroll
        for (int q = 0; q < 4; q++) { xr[q] = xp[q]; tr[q] = tp[q]; }
#pragma unroll
        for (int q = 0; q < 8; q++) { hr[q] = hp[q]; mr[q] = mp[q]; }
    }

    for (int idx = threadIdx.x; idx < H * 2 * H; idx += NTPB) {
        int j = idx >> 6, k = idx & 63;
        sN1t[k][j] = nW1[idx];
    }
    for (int idx = threadIdx.x; idx < H * H; idx += NTPB) {
        int j = idx >> 5, k = idx & 31;
        sN2t[k][j] = nW2[idx];
        if (eW1n) {
            sEAt[k][j] = eW1n[j * 68 + k];
            sEBt[k][j] = eW1n[j * 68 + 32 + k];
        }
    }
    __syncthreads();

    if (!active) return;

    float inv = 1.0f / fmaxf(cnt, 1.0f);
    const float4 z4 = make_float4(0.f, 0.f, 0.f, 0.f);

    float xv[DX];
    float4* xp = (float4*)&g_x[i * DX];
    float4* tp = (float4*)&g_tagg[i * DX];
#pragma unroll
    for (int q = 0; q < 4; q++) {
        xv[4*q]   = xr[q].x + tr[q].x * inv;
        xv[4*q+1] = xr[q].y + tr[q].y * inv;
        xv[4*q+2] = xr[q].z + tr[q].z * inv;
        xv[4*q+3] = xr[q].w + tr[q].w * inv;
        xp[q] = make_float4(xv[4*q], xv[4*q+1], xv[4*q+2], xv[4*q+3]);
        tp[q] = z4;
    }

    float hv[H], mg[H];
    float4* mp = (float4*)&g_magg[i * H];
#pragma unroll
    for (int q = 0; q < 8; q++) {
        hv[4*q] = hr[q].x; hv[4*q+1] = hr[q].y; hv[4*q+2] = hr[q].z; hv[4*q+3] = hr[q].w;
        mg[4*q] = mr[q].x; mg[4*q+1] = mr[q].y; mg[4*q+2] = mr[q].z; mg[4*q+3] = mr[q].w;
        mp[q] = z4;
    }

    float u[H];
#pragma unroll
    for (int j = 0; j < H; j++) u[j] = nb1[j];
#pragma unroll
    for (int k = 0; k < H; k++) {
        float v = hv[k];
        const float4* w4 = (const float4*)&sN1t[k][0];
#pragma unroll
        for (int q = 0; q < 8; q++) {
            float4 w = w4[q];
            u[4*q] += w.x*v; u[4*q+1] += w.y*v; u[4*q+2] += w.z*v; u[4*q+3] += w.w*v;
        }
    }
#pragma unroll
    for (int k = 0; k < H; k++) {
        float v = mg[k];
        const float4* w4 = (const float4*)&sN1t[H + k][0];
#pragma unroll
        for (int q = 0; q < 8; q++) {
            float4 w = w4[q];
            u[4*q] += w.x*v; u[4*q+1] += w.y*v; u[4*q+2] += w.z*v; u[4*q+3] += w.w*v;
        }
    }
#pragma unroll
    for (int j = 0; j < H; j++) u[j] = silu_f(u[j]);

    float hn[H];
#pragma unroll
    for (int j = 0; j < H; j++) hn[j] = nb2[j];
#pragma unroll
    for (int k = 0; k < H; k++) {
        float v = u[k];
        const float4* w4 = (const float4*)&sN2t[k][0];
#pragma unroll
        for (int q = 0; q < 8; q++) {
            float4 w = w4[q];
            hn[4*q] += w.x*v; hn[4*q+1] += w.y*v; hn[4*q+2] += w.z*v; hn[4*q+3] += w.w*v;
        }
    }
#pragma unroll
    for (int j = 0; j < H; j++) hn[j] += hv[j];
    float4* hp = (float4*)&g_h[i * H];
#pragma unroll
    for (int q = 0; q < 8; q++)
        hp[q] = make_float4(hn[4*q], hn[4*q+1], hn[4*q+2], hn[4*q+3]);

    if (eW1n) {
        float Av[H], Bv[H];
#pragma unroll
        for (int j = 0; j < H; j++) { Av[j] = eb1n[j]; Bv[j] = 0.0f; }
#pragma unroll
        for (int k = 0; k < H; k++) {
            float v = hn[k];
            const float4* wa = (const float4*)&sEAt[k][0];
            const float4* wb = (const float4*)&sEBt[k][0];
#pragma unroll
            for (int q = 0; q < 8; q++) {
                float4 a = wa[q], b = wb[q];
                Av[4*q] += a.x*v; Av[4*q+1] += a.y*v; Av[4*q+2] += a.z*v; Av[4*q+3] += a.w*v;
                Bv[4*q] += b.x*v; Bv[4*q+1] += b.y*v; Bv[4*q+2] += b.z*v; Bv[4*q+3] += b.w*v;
            }
        }
        u32 pa[HQ], pb[HQ];
#pragma unroll
        for (int jq = 0; jq < HQ; jq++) {
            pa[jq] = b2u(__floats2bfloat162_rn(Av[2*jq], Av[2*jq+1]));
            pb[jq] = b2u(__floats2bfloat162_rn(Bv[2*jq], Bv[2*jq+1]));
        }
        uint4* Ao = (uint4*)&g_A[i * HQ];
        uint4* Bo = (uint4*)&g_B[i * HQ];
#pragma unroll
        for (int q = 0; q < 4; q++) {
            Ao[q] = make_uint4(pa[4*q], pa[4*q+1], pa[4*q+2], pa[4*q+3]);
            Bo[q] = make_uint4(pb[4*q], pb[4*q+1], pb[4*q+2], pb[4*q+3]);
        }
    }

    if (linW) {
#pragma unroll
        for (int c = 0; c < 3; c++) {
            float acc = 0.0f;
#pragma unroll
            for (int k = 0; k < DX; k++) acc += linW[c * DX + k] * xv[k];
            out[i * 3 + c] = acc;
        }
    }
}

extern "C" void kernel_launch(void* const* d_in, const int* in_sizes, int n_in,
                              void* d_out, int out_size)
{
    const float* node_attrs = (const float*)d_in[0];
    const float* positions  = (const float*)d_in[1];
    const int*   edge_index = (const int*)  d_in[2];
    const float* proj_W     = (const float*)d_in[3];
    const float* emb_in_W   = (const float*)d_in[4];
    const float* emb_in_b   = (const float*)d_in[5];
    const float* edge_W1    = (const float*)d_in[6];
    const float* edge_b1    = (const float*)d_in[7];
    const float* edge_W2    = (const float*)d_in[8];
    const float* edge_b2    = (const float*)d_in[9];
    const float* node_W1    = (const float*)d_in[10];
    const float* node_b1    = (const float*)d_in[11];
    const float* node_W2    = (const float*)d_in[12];
    const float* node_b2    = (const float*)d_in[13];
    const float* coord_W1   = (const float*)d_in[14];
    const float* coord_b1   = (const float*)d_in[15];
    const float* coord_W2   = (const float*)d_in[16];
    const float* lin_W      = (const float*)d_in[19];

    int n = in_sizes[0] / 3;
    int E = in_sizes[2] / 2;
    float* out = (float*)d_out;

    init_kernel<<<(n + 127) / 128, 128>>>(node_attrs, positions, proj_W,
                                          emb_in_W, emb_in_b, edge_W1, edge_b1, n);
    count_kernel<<<(E + 255) / 256, 256>>>(edge_index, E);
    nop_kernel<<<1, 32>>>();

    int eblocks = (E + 2 * ETPB - 1) / (2 * ETPB);
    int nblocks = (n + NTPB - 1) / NTPB;

    for (int l = 0; l < 2; l++) {
        edge_kernel<<<eblocks, ETPB>>>(
            edge_index, E, positions,
            edge_W1 + l * H * 68,
            edge_W2 + l * H * H, edge_b2 + l * H,
            coord_W1 + l * H * H, coord_b1 + l * H,
            coord_W2 + l * H);
        node_kernel<<<nblocks, NTPB>>>(
            node_W1 + l * H * 2 * H, node_b1 + l * H,
            node_W2 + l * H * H,     node_b2 + l * H,
            (l == 0) ? edge_W1 + H * 68 : nullptr,
            (l == 0) ? edge_b1 + H      : nullptr,
            (l == 1) ? lin_W            : nullptr,
            out, n);
    }
}